// round 4
// baseline (speedup 1.0000x reference)
#include <cuda_runtime.h>

// GCN on a complete graph (minus self-loops; GCNConv re-adds them) collapses:
// deg == N for every node and the self-loop exactly replaces the excluded
// h[dst] term, so every node's sym-normalized aggregate is the column-mean of
// the layer input. Hence:
//   v1 = relu(mean_rows(x) @ W1 + b1)   [128]  (uniform across nodes)
//   v2 = relu(v1 @ W2 + b2)             [64]   (uniform across nodes)
//   out[i] = mean(v2)  for all i        (scalar broadcast to 1024)
//
// R3 post-mortem: the 16-block threadFenceReduction version measured 7.55us —
// the __threadfence/atomic/spin machinery dominated (everything <1% utilized).
// This round: ONE block, 1024 threads, zero inter-block sync. x (256 KB) and
// W1/W2 (64 KB) are L2-resident across graph replays; the only real cost is
// ~2.5K L1 wavefronts through one SM (~1.2us) with weight loads issued at
// entry so their L2 latency hides under the x stream.

#define NNODES 1024
#define IND 64
#define HIDD 128
#define OUTD 64

__global__ __launch_bounds__(1024) void gcn_collapsed_kernel(
    const float* __restrict__ x,
    const float* __restrict__ W1,
    const float* __restrict__ b1,
    const float* __restrict__ W2,
    const float* __restrict__ b2,
    float* __restrict__ out)
{
    __shared__ float4 part4[32 * 16];    // 8 KB: per-warp partial column sums
    __shared__ float m[IND];
    __shared__ float v1[HIDD];
    __shared__ float v2[OUTD];
    __shared__ float p2[8][HIDD];        // layer-1 k-chunk partials
    __shared__ float p3[16][OUTD];       // layer-2 k-chunk partials
    __shared__ float s_scalar;

    const int tid  = threadIdx.x;
    const int lane = tid & 31;
    const int warp = tid >> 5;

    // Matvec work mappings (used for both prefetch and compute)
    const int col2 = tid & (HIDD - 1), ch2 = tid >> 7;   // 128 cols x 8 chunks
    const int col3 = tid & (OUTD - 1), ch3 = tid >> 6;   // 64 cols x 16 chunks

    // ---- Issue weight/bias prefetch FIRST: latency hides under x stream ----
    float w1r[8], w2r[8];
    #pragma unroll
    for (int kk = 0; kk < 8; kk++)
        w1r[kk] = W1[(ch2 * 8 + kk) * HIDD + col2];
    #pragma unroll
    for (int kk = 0; kk < 8; kk++)
        w2r[kk] = W2[(ch3 * 8 + kk) * OUTD + col3];
    float bb1 = (tid < HIDD) ? b1[tid] : 0.f;
    float bb2 = (tid < OUTD) ? b2[tid] : 0.f;

    // ---- Phase 1: column sums of x [1024 x 64] via float4 (16 vec-columns) ----
    // thread -> (row group rg = tid>>4 in 0..63, float4-column c4 = tid&15);
    // 16 independent LDG.128 per thread (MLP=16), fully coalesced.
    const int c4 = tid & 15;
    const int rg = tid >> 4;
    const float4* __restrict__ x4 = (const float4*)x;
    float4 acc = make_float4(0.f, 0.f, 0.f, 0.f);
    #pragma unroll
    for (int r = 0; r < NNODES / 64; r++) {
        float4 v = x4[(rg + r * 64) * 16 + c4];
        acc.x += v.x; acc.y += v.y; acc.z += v.z; acc.w += v.w;
    }
    // lanes l and l+16 share c4 (adjacent row groups): fold once
    acc.x += __shfl_down_sync(0xffffffffu, acc.x, 16);
    acc.y += __shfl_down_sync(0xffffffffu, acc.y, 16);
    acc.z += __shfl_down_sync(0xffffffffu, acc.z, 16);
    acc.w += __shfl_down_sync(0xffffffffu, acc.w, 16);
    if (lane < 16) part4[warp * 16 + lane] = acc;
    __syncthreads();

    if (tid < 16) {
        float4 t = make_float4(0.f, 0.f, 0.f, 0.f);
        #pragma unroll
        for (int w = 0; w < 32; w++) {
            float4 v = part4[w * 16 + tid];
            t.x += v.x; t.y += v.y; t.z += v.z; t.w += v.w;
        }
        const float inv = 1.0f / (float)NNODES;
        m[tid * 4 + 0] = t.x * inv;
        m[tid * 4 + 1] = t.y * inv;
        m[tid * 4 + 2] = t.z * inv;
        m[tid * 4 + 3] = t.w * inv;
    }
    __syncthreads();

    // ---- Phase 2: v1 = relu(m @ W1 + b1); weights already in registers ----
    {
        float a = 0.f;
        #pragma unroll
        for (int kk = 0; kk < 8; kk++)
            a = fmaf(m[ch2 * 8 + kk], w1r[kk], a);
        p2[ch2][col2] = a;
    }
    __syncthreads();
    if (tid < HIDD) {
        float a = bb1;
        #pragma unroll
        for (int c = 0; c < 8; c++) a += p2[c][tid];
        v1[tid] = fmaxf(a, 0.f);
    }
    __syncthreads();

    // ---- Phase 3: v2 = relu(v1 @ W2 + b2); weights already in registers ----
    {
        float a = 0.f;
        #pragma unroll
        for (int kk = 0; kk < 8; kk++)
            a = fmaf(v1[ch3 * 8 + kk], w2r[kk], a);
        p3[ch3][col3] = a;
    }
    __syncthreads();
    if (tid < OUTD) {
        float a = bb2;
        #pragma unroll
        for (int c = 0; c < 16; c++) a += p3[c][tid];
        v2[tid] = fmaxf(a, 0.f);
    }
    __syncthreads();

    // ---- Phase 4: scalar = mean(v2) ----
    if (tid < 32) {
        float a = v2[tid] + v2[tid + 32];
        #pragma unroll
        for (int o = 16; o > 0; o >>= 1)
            a += __shfl_down_sync(0xffffffffu, a, o);
        if (tid == 0) s_scalar = a * (1.0f / (float)OUTD);
    }
    __syncthreads();

    // ---- Broadcast scalar to all 1024 outputs ----
    out[tid] = s_scalar;
}

extern "C" void kernel_launch(void* const* d_in, const int* in_sizes, int n_in,
                              void* d_out, int out_size) {
    const float* x  = (const float*)d_in[0];
    const float* W1 = (const float*)d_in[1];
    const float* b1 = (const float*)d_in[2];
    const float* W2 = (const float*)d_in[3];
    const float* b2 = (const float*)d_in[4];
    // d_in[5]=src, d_in[6]=dst: complete graph -> aggregation collapses to a
    // column mean; edge lists are provably unused.
    float* out = (float*)d_out;
    gcn_collapsed_kernel<<<1, 1024>>>(x, W1, b1, W2, b2, out);
}

// round 6
// speedup vs baseline: 1.2651x; 1.2651x over previous
#include <cuda_runtime.h>
#include <cstdint>

// GCN on a complete graph collapses algebraically (deg==N everywhere; the
// self-loop exactly replaces the excluded h[dst] term):
//   v1 = relu(mean_rows(x) @ W1 + b1); v2 = relu(v1 @ W2 + b2);
//   out[i] = mean(v2) for all i  (scalar broadcast to 1024).
//
// R4 evidence: ONE SM is DRAM-fetch-bound at ~44 GB/s (340 KB moved in 7.7us;
// inputs not L2-resident across replays). R3 evidence: gpu-scope
// fence/atomic/spin sync costs ~5us. Design: 8-CTA cluster (8x read BW),
// partial column-sums pushed to rank 0 via one v4 DSMEM store per thread,
// one cluster barrier (~380cyc), rank 0 finishes the tiny matvecs with
// weights prefetched into registers (latency hidden under the x stream).

#define NNODES 1024
#define IND 64
#define HIDD 128
#define OUTD 64
#define CSZ 8
#define ROWS_PER_CTA (NNODES / CSZ)   // 128

__device__ __forceinline__ uint32_t smem_u32(const void* p) {
    uint32_t a;
    asm("{ .reg .u64 t; cvta.to.shared.u64 t, %1; cvt.u32.u64 %0, t; }"
        : "=r"(a) : "l"(p));
    return a;
}

__global__ __launch_bounds__(1024, 1) __cluster_dims__(CSZ, 1, 1)
void gcn_cluster_kernel(
    const float* __restrict__ x,
    const float* __restrict__ W1,
    const float* __restrict__ b1,
    const float* __restrict__ W2,
    const float* __restrict__ b2,
    float* __restrict__ out)
{
    __shared__ float4 part4[32 * 16];        // 8 KB per-warp partials
    __shared__ float4 slots4[CSZ][16];       // rank 0 receives CTA partials here
    __shared__ float  m[IND];
    __shared__ float  v1[HIDD];
    __shared__ float  v2[OUTD];
    __shared__ float  p2[8][HIDD];
    __shared__ float  p3[16][OUTD];
    __shared__ float  s_scalar;

    const int tid  = threadIdx.x;
    const int lane = tid & 31;
    const int warp = tid >> 5;

    uint32_t rank;
    asm("mov.u32 %0, %%cluster_ctarank;" : "=r"(rank));

    const int col2 = tid & (HIDD - 1), ch2 = tid >> 7;   // 128 cols x 8 chunks
    const int col3 = tid & (OUTD - 1), ch3 = tid >> 6;   // 64 cols x 16 chunks

    // ---- Rank 0: weight/bias prefetch FIRST (latency hides under x stream) ----
    float w1r[8], w2r[8], bb1 = 0.f, bb2 = 0.f;
    if (rank == 0) {
        #pragma unroll
        for (int kk = 0; kk < 8; kk++)
            w1r[kk] = W1[(ch2 * 8 + kk) * HIDD + col2];
        #pragma unroll
        for (int kk = 0; kk < 8; kk++)
            w2r[kk] = W2[(ch3 * 8 + kk) * OUTD + col3];
        if (tid < HIDD) bb1 = b1[tid];
        if (tid < OUTD) bb2 = b2[tid];
    }

    // ---- Phase 1: this CTA's 128-row slice of x; 2 x LDG.128 per thread ----
    const int c4 = tid & 15;            // float4 column 0..15
    const int rg = tid >> 4;            // row group 0..63
    const int base = (int)rank * ROWS_PER_CTA;
    const float4* __restrict__ x4 = (const float4*)x;
    float4 a0 = x4[(base + rg) * 16 + c4];
    float4 a1 = x4[(base + rg + 64) * 16 + c4];
    a0.x += a1.x; a0.y += a1.y; a0.z += a1.z; a0.w += a1.w;

    // lanes l and l+16 share c4 (adjacent row groups): fold once
    a0.x += __shfl_down_sync(0xffffffffu, a0.x, 16);
    a0.y += __shfl_down_sync(0xffffffffu, a0.y, 16);
    a0.z += __shfl_down_sync(0xffffffffu, a0.z, 16);
    a0.w += __shfl_down_sync(0xffffffffu, a0.w, 16);
    if (lane < 16) part4[warp * 16 + lane] = a0;
    __syncthreads();

    // 16 threads fold 32 warp partials, then ONE v4 DSMEM store each to rank 0
    if (tid < 16) {
        float4 t = make_float4(0.f, 0.f, 0.f, 0.f);
        #pragma unroll
        for (int w = 0; w < 32; w++) {
            float4 v = part4[w * 16 + tid];
            t.x += v.x; t.y += v.y; t.z += v.z; t.w += v.w;
        }
        uint32_t laddr = smem_u32(&slots4[rank][tid]);
        uint32_t raddr;
        asm("mapa.shared::cluster.u32 %0, %1, %2;" : "=r"(raddr) : "r"(laddr), "r"(0));
        asm volatile("st.shared::cluster.v4.f32 [%0], {%1, %2, %3, %4};"
                     :: "r"(raddr), "f"(t.x), "f"(t.y), "f"(t.z), "f"(t.w));
    }

    // ---- Cluster barrier: arrive (release) orders the DSMEM stores ----
    asm volatile("barrier.cluster.arrive.aligned;" ::: "memory");
    if (rank != 0) return;                 // producers exit; no one targets them
    asm volatile("barrier.cluster.wait.aligned;" ::: "memory");

    // ---- Rank 0: combine 8 partials -> column mean ----
    if (tid < IND) {
        const float* s0 = (const float*)&slots4[0][0];
        float s = 0.f;
        #pragma unroll
        for (int r = 0; r < CSZ; r++) s += s0[r * IND + tid];
        m[tid] = s * (1.0f / (float)NNODES);
    }
    __syncthreads();

    // ---- Phase 2: v1 = relu(m @ W1 + b1) (weights in registers) ----
    {
        float a = 0.f;
        #pragma unroll
        for (int kk = 0; kk < 8; kk++)
            a = fmaf(m[ch2 * 8 + kk], w1r[kk], a);
        p2[ch2][col2] = a;
    }
    __syncthreads();
    if (tid < HIDD) {
        float a = bb1;
        #pragma unroll
        for (int c = 0; c < 8; c++) a += p2[c][tid];
        v1[tid] = fmaxf(a, 0.f);
    }
    __syncthreads();

    // ---- Phase 3: v2 = relu(v1 @ W2 + b2) ----
    {
        float a = 0.f;
        #pragma unroll
        for (int kk = 0; kk < 8; kk++)
            a = fmaf(v1[ch3 * 8 + kk], w2r[kk], a);
        p3[ch3][col3] = a;
    }
    __syncthreads();
    if (tid < OUTD) {
        float a = bb2;
        #pragma unroll
        for (int c = 0; c < 16; c++) a += p3[c][tid];
        v2[tid] = fmaxf(a, 0.f);
    }
    __syncthreads();

    // ---- Phase 4: scalar = mean(v2); broadcast to all 1024 outputs ----
    if (tid < 32) {
        float a = v2[tid] + v2[tid + 32];
        #pragma unroll
        for (int o = 16; o > 0; o >>= 1)
            a += __shfl_down_sync(0xffffffffu, a, o);
        if (tid == 0) s_scalar = a * (1.0f / (float)OUTD);
    }
    __syncthreads();
    out[tid] = s_scalar;
}

extern "C" void kernel_launch(void* const* d_in, const int* in_sizes, int n_in,
                              void* d_out, int out_size) {
    const float* x  = (const float*)d_in[0];
    const float* W1 = (const float*)d_in[1];
    const float* b1 = (const float*)d_in[2];
    const float* W2 = (const float*)d_in[3];
    const float* b2 = (const float*)d_in[4];
    // d_in[5]=src, d_in[6]=dst unused: complete graph -> column-mean collapse.
    float* out = (float*)d_out;
    gcn_cluster_kernel<<<CSZ, 1024>>>(x, W1, b1, W2, b2, out);
}